// round 8
// baseline (speedup 1.0000x reference)
#include <cuda_runtime.h>

// CLIP_AD pooling: patch_tokens [B=512, 225, D=896] f32 -> out [B, 366, 896]:
//   groups   0..168 : mean over 3x3 sliding windows on 15x15 grid (13x13)
//   groups 169..364 : mean over 2x2 sliding windows (14x14)
//   group      365  : mean over all 225 tokens
//
// R7: persistent double-buffered pipeline. 444 CTAs (3/SM), each loops over
// ~32 (b, chunk) tiles. cp.async prefetches tile i+1 into buffer B while the
// CTA computes/stores tile i from buffer A -> continuous overlapped read +
// write streams at the DRAM controller, and no partial-wave tail.

#define GRID15 15
#define NTOK   225
#define DIM    896
#define NGRP   366
#define CHUNK  32            // floats per chunk
#define CH4    (CHUNK / 4)   // 8 float4 per chunk
#define NCHUNK (DIM / CHUNK) // 28
#define TPB    256
#define NB     512
#define NTILE  (NB * NCHUNK) // 14336
#define NCTA   444           // 148 SMs * 3
#define TILE4  (NTOK * CH4)  // 1800 float4 per buffer
#define SMEM_BYTES (2 * TILE4 * 16)  // 57600

__device__ __forceinline__ float4 f4add(float4 a, float4 b) {
    return make_float4(a.x + b.x, a.y + b.y, a.z + b.z, a.w + b.w);
}
__device__ __forceinline__ float4 f4scale(float4 a, float s) {
    return make_float4(a.x * s, a.y * s, a.z * s, a.w * s);
}

__device__ __forceinline__ void stage_tile(const float* __restrict__ tok,
                                           int tile, unsigned s_dst)
{
    const int ROW4 = DIM / 4;
    int b  = tile / NCHUNK;
    int ch = tile - b * NCHUNK;
    const float4* g = reinterpret_cast<const float4*>(
        tok + (size_t)b * NTOK * DIM + (size_t)ch * CHUNK);
    #pragma unroll
    for (int i = threadIdx.x; i < TILE4; i += TPB) {
        int t = i >> 3;
        int c = i & 7;
        unsigned dst = s_dst + (unsigned)i * 16u;
        const float4* src = g + t * ROW4 + c;
        asm volatile("cp.async.cg.shared.global [%0], [%1], 16;\n"
                     :: "r"(dst), "l"(src));
    }
}

__global__ __launch_bounds__(TPB) void clip_pool_kernel(
    const float* __restrict__ tok, float* __restrict__ out)
{
    extern __shared__ float4 s[];  // 2 buffers of TILE4 float4
    const int ROW4 = DIM / 4;

    unsigned s_base = (unsigned)__cvta_generic_to_shared(s);

    const int col  = threadIdx.x & 7;   // float4 lane within chunk (0..7)
    const int grow = threadIdx.x >> 3;  // task row (0..31)

    // prefetch first tile into buffer 0
    int tile0 = blockIdx.x;
    if (tile0 < NTILE) stage_tile(tok, tile0, s_base);
    asm volatile("cp.async.commit_group;\n" ::: "memory");

    int buf = 0;
    for (int tile = tile0; tile < NTILE; tile += NCTA) {
        // prefetch next tile into the other buffer
        int nxt = tile + NCTA;
        if (nxt < NTILE)
            stage_tile(tok, nxt, s_base + (unsigned)((buf ^ 1) * TILE4) * 16u);
        asm volatile("cp.async.commit_group;\n" ::: "memory");
        // wait until only the just-committed group is pending -> current done
        asm volatile("cp.async.wait_group 1;\n" ::: "memory");
        __syncthreads();

        const float4* sb = s + buf * TILE4;

        int b  = tile / NCHUNK;
        int ch = tile - b * NCHUNK;
        float4* g_out = reinterpret_cast<float4*>(
            out + (size_t)b * NGRP * DIM + (size_t)ch * CHUNK);

        if (grow < 13) {
            // ---- 3x3 windows, output row = grow ----
            const float4* r0 = sb + ((grow    ) * GRID15) * CH4 + col;
            const float4* r1 = sb + ((grow + 1) * GRID15) * CH4 + col;
            const float4* r2 = sb + ((grow + 2) * GRID15) * CH4 + col;
            float4 v0 = f4add(f4add(r0[0 * CH4], r1[0 * CH4]), r2[0 * CH4]);
            float4 v1 = f4add(f4add(r0[1 * CH4], r1[1 * CH4]), r2[1 * CH4]);
            const float inv9 = 1.0f / 9.0f;
            #pragma unroll
            for (int c = 0; c < 13; c++) {
                float4 v2 = f4add(f4add(r0[(c + 2) * CH4], r1[(c + 2) * CH4]),
                                  r2[(c + 2) * CH4]);
                float4 res = f4scale(f4add(f4add(v0, v1), v2), inv9);
                g_out[(size_t)(grow * 13 + c) * ROW4 + col] = res;
                v0 = v1; v1 = v2;
            }
        } else if (grow < 27) {
            // ---- 2x2 windows, output row = grow - 13 ----
            const int rr = grow - 13;
            const float4* r0 = sb + ((rr    ) * GRID15) * CH4 + col;
            const float4* r1 = sb + ((rr + 1) * GRID15) * CH4 + col;
            float4 v0 = f4add(r0[0], r1[0]);
            #pragma unroll
            for (int c = 0; c < 14; c++) {
                float4 v1 = f4add(r0[(c + 1) * CH4], r1[(c + 1) * CH4]);
                float4 res = f4scale(f4add(v0, v1), 0.25f);
                g_out[(size_t)(169 + rr * 14 + c) * ROW4 + col] = res;
                v0 = v1;
            }
        } else if (grow >= 28) {
            // ---- class token: grows 28..31 split 225 tokens 4 ways ----
            const int sub   = grow - 28;
            const int start = (NTOK * sub) / 4;
            const int end   = (NTOK * (sub + 1)) / 4;
            float4 acc = make_float4(0.f, 0.f, 0.f, 0.f);
            for (int t = start; t < end; t++) {
                float4 v = sb[t * CH4 + col];
                acc.x += v.x; acc.y += v.y; acc.z += v.z; acc.w += v.w;
            }
            #pragma unroll
            for (int m = 8; m <= 16; m <<= 1) {
                acc.x += __shfl_xor_sync(0xffffffffu, acc.x, m);
                acc.y += __shfl_xor_sync(0xffffffffu, acc.y, m);
                acc.z += __shfl_xor_sync(0xffffffffu, acc.z, m);
                acc.w += __shfl_xor_sync(0xffffffffu, acc.w, m);
            }
            if (sub == 0)
                g_out[(size_t)365 * ROW4 + col] = f4scale(acc, 1.0f / 225.0f);
        }

        buf ^= 1;
        // make sure everyone is done reading this buffer before the next
        // iteration's prefetch overwrites it
        __syncthreads();
    }
}

extern "C" void kernel_launch(void* const* d_in, const int* in_sizes, int n_in,
                              void* d_out, int out_size)
{
    (void)in_sizes; (void)n_in; (void)out_size;
    const float* tok = (const float*)d_in[0];
    // d_in[1]/d_in[2] (masks) are deterministic sliding-window tables,
    // reproduced arithmetically in-kernel.
    float* out = (float*)d_out;

    static bool attr_set = false;
    if (!attr_set) {
        cudaFuncSetAttribute(clip_pool_kernel,
                             cudaFuncAttributeMaxDynamicSharedMemorySize,
                             SMEM_BYTES);
        attr_set = true;
    }

    clip_pool_kernel<<<NCTA, TPB, SMEM_BYTES>>>(tok, out);
}

// round 9
// speedup vs baseline: 1.1860x; 1.1860x over previous
#include <cuda_runtime.h>

// CLIP_AD pooling: patch_tokens [B=512, 225, D=896] f32 -> out [B, 366, 896]:
//   groups   0..168 : mean over 3x3 sliding windows on 15x15 grid (13x13)
//   groups 169..364 : mean over 2x2 sliding windows (14x14)
//   group      365  : mean over all 225 tokens
//
// R8: R6 structure (non-persistent, cp.async staging), CHUNK 32->64 and
// TPB 256->512: 256B contiguous per token read / per group store (bigger DRAM
// bursts, half the requests), 3 CTAs/SM x 512thr = 48 warps. Streaming
// stores (__stcs) keep never-reread output out of L2.

#define GRID15 15
#define NTOK   225
#define DIM    896
#define NGRP   366
#define CHUNK  64            // floats per chunk
#define CH4    (CHUNK / 4)   // 16 float4 per chunk
#define NCHUNK (DIM / CHUNK) // 14
#define TPB    512
#define TILE4  (NTOK * CH4)  // 3600 float4 = 57600 B
#define SMEM_BYTES (TILE4 * 16)

__device__ __forceinline__ float4 f4add(float4 a, float4 b) {
    return make_float4(a.x + b.x, a.y + b.y, a.z + b.z, a.w + b.w);
}
__device__ __forceinline__ float4 f4scale(float4 a, float s) {
    return make_float4(a.x * s, a.y * s, a.z * s, a.w * s);
}

__global__ __launch_bounds__(TPB) void clip_pool_kernel(
    const float* __restrict__ tok, float* __restrict__ out)
{
    extern __shared__ float4 s[];  // [225][16] float4

    const int b  = blockIdx.y;
    const int ch = blockIdx.x;
    const int ROW4 = DIM / 4;  // 224 float4 per token row in gmem

    // ---- stage token slice [225, 64 floats] into smem via cp.async ----
    const float4* g_tok = reinterpret_cast<const float4*>(
        tok + (size_t)b * NTOK * DIM + (size_t)ch * CHUNK);
    unsigned s_base = (unsigned)__cvta_generic_to_shared(s);

    #pragma unroll
    for (int i = threadIdx.x; i < TILE4; i += TPB) {
        int t = i >> 4;            // token
        int c = i & 15;            // float4 within chunk
        unsigned dst = s_base + (unsigned)i * 16u;
        const float4* src = g_tok + t * ROW4 + c;
        asm volatile("cp.async.cg.shared.global [%0], [%1], 16;\n"
                     :: "r"(dst), "l"(src));
    }
    asm volatile("cp.async.commit_group;\n" ::: "memory");
    asm volatile("cp.async.wait_group 0;\n" ::: "memory");
    __syncthreads();

    const int col  = threadIdx.x & 15;  // float4 lane within chunk (0..15)
    const int grow = threadIdx.x >> 4;  // task row (0..31)

    float4* g_out = reinterpret_cast<float4*>(
        out + (size_t)b * NGRP * DIM + (size_t)ch * CHUNK);

    if (grow < 13) {
        // ---- 3x3 windows, output row = grow ----
        const float4* r0 = s + ((grow    ) * GRID15) * CH4 + col;
        const float4* r1 = s + ((grow + 1) * GRID15) * CH4 + col;
        const float4* r2 = s + ((grow + 2) * GRID15) * CH4 + col;
        float4 v0 = f4add(f4add(r0[0 * CH4], r1[0 * CH4]), r2[0 * CH4]);
        float4 v1 = f4add(f4add(r0[1 * CH4], r1[1 * CH4]), r2[1 * CH4]);
        const float inv9 = 1.0f / 9.0f;
        #pragma unroll
        for (int c = 0; c < 13; c++) {
            float4 v2 = f4add(f4add(r0[(c + 2) * CH4], r1[(c + 2) * CH4]),
                              r2[(c + 2) * CH4]);
            float4 res = f4scale(f4add(f4add(v0, v1), v2), inv9);
            __stcs(&g_out[(size_t)(grow * 13 + c) * ROW4 + col], res);
            v0 = v1; v1 = v2;
        }
    } else if (grow < 27) {
        // ---- 2x2 windows, output row = grow - 13 ----
        const int rr = grow - 13;
        const float4* r0 = s + ((rr    ) * GRID15) * CH4 + col;
        const float4* r1 = s + ((rr + 1) * GRID15) * CH4 + col;
        float4 v0 = f4add(r0[0], r1[0]);
        #pragma unroll
        for (int c = 0; c < 14; c++) {
            float4 v1 = f4add(r0[(c + 1) * CH4], r1[(c + 1) * CH4]);
            float4 res = f4scale(f4add(v0, v1), 0.25f);
            __stcs(&g_out[(size_t)(169 + rr * 14 + c) * ROW4 + col], res);
            v0 = v1;
        }
    } else if (grow == 28 || grow == 29) {
        // ---- class token: warp 14's two lane-sets split 225 tokens,
        //      shfl_xor(16) combines across the half-warps. ----
        const int sub   = grow - 28;             // 0 or 1
        const int start = sub ? 113 : 0;
        const int end   = sub ? 225 : 113;
        float4 acc = make_float4(0.f, 0.f, 0.f, 0.f);
        for (int t = start; t < end; t++) {
            float4 v = s[t * CH4 + col];
            acc.x += v.x; acc.y += v.y; acc.z += v.z; acc.w += v.w;
        }
        acc.x += __shfl_xor_sync(0xffffffffu, acc.x, 16);
        acc.y += __shfl_xor_sync(0xffffffffu, acc.y, 16);
        acc.z += __shfl_xor_sync(0xffffffffu, acc.z, 16);
        acc.w += __shfl_xor_sync(0xffffffffu, acc.w, 16);
        if (sub == 0)
            __stcs(&g_out[(size_t)365 * ROW4 + col], f4scale(acc, 1.0f / 225.0f));
    }
    // grows 27, 30, 31: idle in phase 2 (helped with staging)
}

extern "C" void kernel_launch(void* const* d_in, const int* in_sizes, int n_in,
                              void* d_out, int out_size)
{
    (void)in_sizes; (void)n_in; (void)out_size;
    const float* tok = (const float*)d_in[0];
    // d_in[1]/d_in[2] (masks) are deterministic sliding-window tables,
    // reproduced arithmetically in-kernel.
    float* out = (float*)d_out;

    static bool attr_set = false;
    if (!attr_set) {
        cudaFuncSetAttribute(clip_pool_kernel,
                             cudaFuncAttributeMaxDynamicSharedMemorySize,
                             SMEM_BYTES);
        attr_set = true;
    }

    dim3 grid(NCHUNK, 512);
    clip_pool_kernel<<<grid, TPB, SMEM_BYTES>>>(tok, out);
}